// round 1
// baseline (speedup 1.0000x reference)
#include <cuda_runtime.h>
#include <cstdint>

#define BB   2
#define NN   8192
#define KK   10
#define TPB  128
#define TILE 1024

// Scratch (no device allocation allowed)
__device__ float4 g_pts[BB * NN];  // {x, y, z, |p|^2} of point1
__device__ float4 g_q[BB * NN];    // {p1-p2, unused}
__device__ float  g_acc;

__global__ void prep_kernel(const float* __restrict__ p1,
                            const float* __restrict__ p2) {
    int i = blockIdx.x * blockDim.x + threadIdx.x;
    if (i == 0) g_acc = 0.0f;
    if (i < BB * NN) {
        float x = p1[3 * i + 0], y = p1[3 * i + 1], z = p1[3 * i + 2];
        float a = p2[3 * i + 0], b = p2[3 * i + 1], c = p2[3 * i + 2];
        g_pts[i] = make_float4(x, y, z, x * x + y * y + z * z);
        g_q[i]   = make_float4(x - a, y - b, z - c, 0.0f);
    }
}

__global__ __launch_bounds__(TPB, 1) void knn_loss_kernel() {
    __shared__ float4 tile[TILE];
    __shared__ float  wsum[TPB / 32];

    const int b  = blockIdx.y;
    const int qi = blockIdx.x * TPB + threadIdx.x;  // query index in batch
    const float4* __restrict__ pts = g_pts + b * NN;

    const float4 me = pts[qi];

    float dist[KK];
    int   nn[KK];
#pragma unroll
    for (int k = 0; k < KK; ++k) {
        dist[k] = __int_as_float(0x7f800000);  // +inf
        nn[k]   = -1;
    }

    for (int t = 0; t < NN; t += TILE) {
        // cooperative tile load
#pragma unroll
        for (int j = threadIdx.x; j < TILE; j += TPB)
            tile[j] = pts[t + j];
        __syncthreads();

#pragma unroll 8
        for (int j = 0; j < TILE; ++j) {
            float4 c  = tile[j];
            float dot = me.x * c.x + me.y * c.y + me.z * c.z;
            // reference formula: d2 = sq_i + sq_j - 2*dot  (keeps ordering aligned)
            float d2  = (me.w + c.w) - 2.0f * dot;
            int   gj  = t + j;
            if (d2 < dist[KK - 1] && gj != qi) {
                dist[KK - 1] = d2;
                nn[KK - 1]   = gj;
#pragma unroll
                for (int k = KK - 1; k > 0; --k) {
                    if (dist[k] < dist[k - 1]) {
                        float td = dist[k]; dist[k] = dist[k - 1]; dist[k - 1] = td;
                        int   ti = nn[k];   nn[k]   = nn[k - 1];   nn[k - 1]   = ti;
                    } else {
                        break;
                    }
                }
            }
        }
        __syncthreads();
    }

    // lap1 - lap2 = mean_k q[nbr_k] - q_i,  q = p1 - p2
    const float4* __restrict__ qv = g_q + b * NN;
    float sx = 0.0f, sy = 0.0f, sz = 0.0f;
#pragma unroll
    for (int k = 0; k < KK; ++k) {
        float4 v = __ldg(&qv[nn[k]]);
        sx += v.x; sy += v.y; sz += v.z;
    }
    float4 myq = qv[qi];
    const float inv_k = 1.0f / (float)KK;
    float lx = sx * inv_k - myq.x;
    float ly = sy * inv_k - myq.y;
    float lz = sz * inv_k - myq.z;
    float contrib = fabsf(lx) + fabsf(ly) + fabsf(lz);

    // block reduction
#pragma unroll
    for (int off = 16; off > 0; off >>= 1)
        contrib += __shfl_down_sync(0xffffffffu, contrib, off);
    if ((threadIdx.x & 31) == 0) wsum[threadIdx.x >> 5] = contrib;
    __syncthreads();
    if (threadIdx.x == 0) {
        float s = 0.0f;
#pragma unroll
        for (int w = 0; w < TPB / 32; ++w) s += wsum[w];
        atomicAdd(&g_acc, s);
    }
}

__global__ void finalize_kernel(float* __restrict__ out) {
    out[0] = g_acc * (1.0f / (float)(BB * NN * 3));
}

extern "C" void kernel_launch(void* const* d_in, const int* in_sizes, int n_in,
                              void* d_out, int out_size) {
    const float* p1 = (const float*)d_in[0];
    const float* p2 = (const float*)d_in[1];
    float* out = (float*)d_out;

    prep_kernel<<<(BB * NN + 255) / 256, 256>>>(p1, p2);
    dim3 grid(NN / TPB, BB);
    knn_loss_kernel<<<grid, TPB>>>();
    finalize_kernel<<<1, 1>>>(out);
}